// round 2
// baseline (speedup 1.0000x reference)
#include <cuda_runtime.h>

// RankCoxHazardLoss — B=512 rows, N=256 items per row.
// Kernel 1: one CTA per row, thread i owns item i, two serial j-loops over SMEM.
// Kernel 2: deterministic tree reduction of per-row partials to the scalar.
// valid_mask dtype is detected at runtime from its bit patterns (bool may be
// stored as uint8, int32, float32, or bf16 depending on harness conversion).

#define EPSF 1e-7f
static constexpr int BB = 512;
static constexpr int NN = 256;

__device__ float g_row_cox[BB];   // vb * total_b
__device__ float g_row_vb[BB];    // valid_batch flag
__device__ float g_row_rank[BB];  // rank_sum_b / max(num_pairs_b, 1)

__global__ __launch_bounds__(NN) void row_kernel(
    const float* __restrict__ pred,
    const float* __restrict__ target,
    const void*  __restrict__ validp)
{
    __shared__ float s_tm[NN];    // masked target (valid ? t : -1)
    __shared__ float s_e[NN];     // exp(pred)
    __shared__ float s_rinv[NN];  // exp(-pred)
    __shared__ float s_p[NN];     // pred (for exact strict compares)
    __shared__ float s_wm[8], s_wc[8];            // warp max / valid-count
    __shared__ float s_rl[8], s_rr[8], s_rn[8];   // warp partial sums

    const int b = blockIdx.x;
    const int i = threadIdx.x;
    const int lane = i & 31;
    const int wid  = i >> 5;
    const int idx  = b * NN + i;

    // ---- detect valid_mask dtype from first 256 words of the buffer ----
    // uint8-packed bools: words have 0/1 bytes -> some word & 0xFFFFFF00 != 0
    // int32 bools:        words in {0,1}
    // float32 bools:      words in {0, 0x3F800000}
    // bf16 bools:         words in {0, 0x3F80, 0x3F800000, 0x3F803F80}
    const unsigned int w = ((const unsigned int*)validp)[i];
    const int any_bf = __syncthreads_or((w == 0x3F803F80u) || (w == 0x00003F80u));
    const int any_f  = __syncthreads_or(w == 0x3F800000u);
    const int any_mb = __syncthreads_or((w & 0xFFFFFF00u) != 0u &&
                                        w != 0x3F800000u && w != 0x3F803F80u &&
                                        w != 0x00003F80u);
    bool v_i;
    if (any_bf)                      // bf16 (two elems per word)
        v_i = ((const unsigned short*)validp)[idx] != 0;
    else if (any_f)                  // float32
        v_i = ((const float*)validp)[idx] != 0.0f;
    else if (any_mb)                 // uint8 / bool bytes
        v_i = ((const unsigned char*)validp)[idx] != 0;
    else                             // int32
        v_i = ((const int*)validp)[idx] != 0;

    const float p_i  = pred[idx];
    const float t_i  = target[idx];
    const float tm_i = v_i ? t_i : -1.0f;
    const float e_i  = __expf(p_i);

    s_tm[i]   = tm_i;
    s_e[i]    = e_i;
    s_rinv[i] = __expf(-p_i);
    s_p[i]    = p_i;
    __syncthreads();

    // ---- block-wide: max masked time, valid count ----
    float m  = tm_i;
    float vc = v_i ? 1.0f : 0.0f;
    #pragma unroll
    for (int o = 16; o; o >>= 1) {
        m  = fmaxf(m, __shfl_xor_sync(0xffffffffu, m, o));
        vc +=        __shfl_xor_sync(0xffffffffu, vc, o);
    }
    if (lane == 0) { s_wm[wid] = m; s_wc[wid] = vc; }
    __syncthreads();
    float bmax = s_wm[0], vcnt = s_wc[0];
    #pragma unroll
    for (int k = 1; k < 8; k++) { bmax = fmaxf(bmax, s_wm[k]); vcnt += s_wc[k]; }

    const bool elim = (tm_i < bmax) && (tm_i > 0.0f) && v_i;

    // ---- pass 1: risk-set denominator + rank pairs (pure ALU/FMA) ----
    float den  = 0.0f;   // sum of e_j over risk set (includes j==i)
    float rsum = 0.0f;   // sum of exp(p_i - p_j) over violations
    float np   = 0.0f;   // count of target pairs
    #pragma unroll 8
    for (int j = 0; j < NN; j++) {
        const float tmj = s_tm[j];
        const float ej  = s_e[j];
        if (tmj >= tm_i) den += ej;                    // risk set
        const bool tp = (tmj >= 0.0f) && (tmj < t_i); // valid_j && t_i > t_j
        if (tp) {
            np += 1.0f;
            if (p_i > s_p[j]) rsum += e_i * s_rinv[j];
        }
    }
    if (!v_i) { np = 0.0f; rsum = 0.0f; }

    // ---- pass 2: surviving-term product (one log per i) ----
    // sum_j -log(1 - p_j + eps) = -log( prod_j (1 - p_j + eps) )
    const float invden = 1.0f / den;  // den >= e_i > 0 always
    float prod = 1.0f;
    #pragma unroll 8
    for (int j = 0; j < NN; j++) {
        const float tmj = s_tm[j];
        const float pj  = fminf(s_e[j] * invden, 1.0f - EPSF);
        const bool risk = (tmj >= tm_i) && (j != i);
        prod *= risk ? (1.0f - pj + EPSF) : 1.0f;
    }
    const float D = __logf(den);
    float loss_i = elim ? (D - p_i) - __logf(prod) : 0.0f;

    // ---- block reduce (loss, rsum, np) — fixed order, deterministic ----
    #pragma unroll
    for (int o = 16; o; o >>= 1) {
        loss_i += __shfl_xor_sync(0xffffffffu, loss_i, o);
        rsum   += __shfl_xor_sync(0xffffffffu, rsum, o);
        np     += __shfl_xor_sync(0xffffffffu, np, o);
    }
    if (lane == 0) { s_rl[wid] = loss_i; s_rr[wid] = rsum; s_rn[wid] = np; }
    __syncthreads();
    if (i == 0) {
        float tl = 0.0f, tr = 0.0f, tn = 0.0f;
        #pragma unroll
        for (int k = 0; k < 8; k++) { tl += s_rl[k]; tr += s_rr[k]; tn += s_rn[k]; }
        const float vb = (vcnt >= 2.0f) ? 1.0f : 0.0f;
        g_row_cox[b]  = vb * tl;
        g_row_vb[b]   = vb;
        g_row_rank[b] = tr / fmaxf(tn, 1.0f);
    }
}

__global__ __launch_bounds__(BB) void reduce_kernel(float* __restrict__ out)
{
    __shared__ float sc[BB], sv[BB], sr[BB];
    const int i = threadIdx.x;
    sc[i] = g_row_cox[i];
    sv[i] = g_row_vb[i];
    sr[i] = g_row_rank[i];
    __syncthreads();
    #pragma unroll
    for (int s = BB / 2; s > 0; s >>= 1) {
        if (i < s) { sc[i] += sc[i + s]; sv[i] += sv[i + s]; sr[i] += sr[i + s]; }
        __syncthreads();
    }
    if (i == 0) {
        out[0] = sc[0] / fmaxf(sv[0], 1.0f) + sr[0] * (1.0f / (float)BB);
    }
}

extern "C" void kernel_launch(void* const* d_in, const int* in_sizes, int n_in,
                              void* d_out, int out_size)
{
    const float* pred   = (const float*)d_in[0];
    const float* target = (const float*)d_in[1];
    const void*  valid  = (const void*)d_in[2];
    float*       out    = (float*)d_out;

    row_kernel<<<BB, NN>>>(pred, target, valid);
    reduce_kernel<<<1, BB>>>(out);
}

// round 3
// speedup vs baseline: 1.5247x; 1.5247x over previous
#include <cuda_runtime.h>

// RankCoxHazardLoss — B=512 rows, N=256 items per row.
// Single fused kernel: one CTA per row; last CTA to finish does the final
// scalar reduction (deterministic: fixed-order tree over g_row arrays).

#define EPSF 1e-7f
static constexpr int BB = 512;
static constexpr int NN = 256;

__device__ float g_row_cox[BB];
__device__ float g_row_vb[BB];
__device__ float g_row_rank[BB];
__device__ unsigned int g_done = 0;

__global__ __launch_bounds__(NN) void fused_kernel(
    const float* __restrict__ pred,
    const float* __restrict__ target,
    const void*  __restrict__ validp,
    float*       __restrict__ out)
{
    __shared__ float2 s_te[NN];   // (masked time, exp(pred))
    __shared__ float2 s_pr[NN];   // (pred, exp(-pred))
    __shared__ float s_wm[8], s_wc[8];
    __shared__ float s_rl[8], s_rr[8], s_rn[8];
    __shared__ unsigned int s_islast;

    const int b    = blockIdx.x;
    const int i    = threadIdx.x;
    const int lane = i & 31;
    const int wid  = i >> 5;
    const int idx  = b * NN + i;

    // ---- detect valid_mask dtype from first 256 words of the buffer ----
    const unsigned int w = ((const unsigned int*)validp)[i];
    const int any_bf = __syncthreads_or((w == 0x3F803F80u) || (w == 0x00003F80u));
    const int any_f  = __syncthreads_or(w == 0x3F800000u);
    const int any_mb = __syncthreads_or((w & 0xFFFFFF00u) != 0u &&
                                        w != 0x3F800000u && w != 0x3F803F80u &&
                                        w != 0x00003F80u);
    bool v_i;
    if (any_bf)      v_i = ((const unsigned short*)validp)[idx] != 0;
    else if (any_f)  v_i = ((const float*)validp)[idx] != 0.0f;
    else if (any_mb) v_i = ((const unsigned char*)validp)[idx] != 0;
    else             v_i = ((const int*)validp)[idx] != 0;

    const float p_i  = pred[idx];
    const float t_i  = target[idx];
    const float tm_i = v_i ? t_i : -1.0f;
    const float e_i  = __expf(p_i);

    s_te[i] = make_float2(tm_i, e_i);
    s_pr[i] = make_float2(p_i, __expf(-p_i));
    __syncthreads();

    // ---- block-wide: max masked time, valid count ----
    float m  = tm_i;
    float vc = v_i ? 1.0f : 0.0f;
    #pragma unroll
    for (int o = 16; o; o >>= 1) {
        m  = fmaxf(m, __shfl_xor_sync(0xffffffffu, m, o));
        vc +=        __shfl_xor_sync(0xffffffffu, vc, o);
    }
    if (lane == 0) { s_wm[wid] = m; s_wc[wid] = vc; }
    __syncthreads();
    float bmax = s_wm[0], vcnt = s_wc[0];
    #pragma unroll
    for (int k = 1; k < 8; k++) { bmax = fmaxf(bmax, s_wm[k]); vcnt += s_wc[k]; }

    const bool elim = (tm_i < bmax) && (tm_i > 0.0f) && v_i;

    // ---- pass 1: risk-set denominator + rank pairs (2 j per LDS.128) ----
    const float4* te4 = (const float4*)s_te;
    const float4* pr4 = (const float4*)s_pr;
    float den0 = 0.0f, den1 = 0.0f;
    float rs0  = 0.0f, rs1  = 0.0f;
    float np0  = 0.0f, np1  = 0.0f;
    #pragma unroll 4
    for (int j2 = 0; j2 < NN / 2; j2++) {
        const float4 te = te4[j2];   // tm0, e0, tm1, e1
        const float4 pr = pr4[j2];   // p0, r0, p1, r1
        if (te.x >= tm_i) den0 += te.y;
        if (te.z >= tm_i) den1 += te.w;
        const bool tp0 = (te.x >= 0.0f) && (te.x < t_i);
        const bool tp1 = (te.z >= 0.0f) && (te.z < t_i);
        if (tp0) { np0 += 1.0f; if (p_i > pr.x) rs0 += e_i * pr.y; }
        if (tp1) { np1 += 1.0f; if (p_i > pr.z) rs1 += e_i * pr.w; }
    }
    float den  = den0 + den1;
    float rsum = rs0 + rs1;
    float np   = np0 + np1;
    if (!v_i) { np = 0.0f; rsum = 0.0f; }

    // ---- pass 2: surviving-term product, diagonal divided out ----
    // term_j = 1 - min(e_j/den, 1-eps) + eps = max((1+eps) - e_j*invden, 2eps)
    const float invden = 1.0f / den;
    const float c1 = 1.0f + EPSF;
    const float c2 = 2.0f * EPSF;
    float pd0 = 1.0f, pd1 = 1.0f;
    #pragma unroll 4
    for (int j2 = 0; j2 < NN / 2; j2++) {
        const float4 te = te4[j2];
        const float t0 = fmaxf(fmaf(-te.y, invden, c1), c2);
        const float t1 = fmaxf(fmaf(-te.w, invden, c1), c2);
        pd0 *= (te.x >= tm_i) ? t0 : 1.0f;
        pd1 *= (te.z >= tm_i) ? t1 : 1.0f;
    }
    const float prod = pd0 * pd1;
    const float own  = fmaxf(fmaf(-e_i, invden, c1), c2);  // j==i term
    float loss_i = 0.0f;
    if (elim)
        loss_i = (__logf(den) - p_i) - __logf(prod) + __logf(own);

    // ---- block reduce (loss, rsum, np) — fixed order, deterministic ----
    #pragma unroll
    for (int o = 16; o; o >>= 1) {
        loss_i += __shfl_xor_sync(0xffffffffu, loss_i, o);
        rsum   += __shfl_xor_sync(0xffffffffu, rsum, o);
        np     += __shfl_xor_sync(0xffffffffu, np, o);
    }
    if (lane == 0) { s_rl[wid] = loss_i; s_rr[wid] = rsum; s_rn[wid] = np; }
    __syncthreads();
    if (i == 0) {
        float tl = 0.0f, tr = 0.0f, tn = 0.0f;
        #pragma unroll
        for (int k = 0; k < 8; k++) { tl += s_rl[k]; tr += s_rr[k]; tn += s_rn[k]; }
        const float vb = (vcnt >= 2.0f) ? 1.0f : 0.0f;
        g_row_cox[b]  = vb * tl;
        g_row_vb[b]   = vb;
        g_row_rank[b] = tr / fmaxf(tn, 1.0f);
        __threadfence();
        const unsigned int t = atomicAdd(&g_done, 1u);
        s_islast = (t == (unsigned int)(BB - 1)) ? 1u : 0u;
    }
    __syncthreads();

    // ---- last block performs the final scalar reduction ----
    if (s_islast) {
        float c = g_row_cox[i]  + g_row_cox[i + NN];
        float v = g_row_vb[i]   + g_row_vb[i + NN];
        float r = g_row_rank[i] + g_row_rank[i + NN];
        #pragma unroll
        for (int o = 16; o; o >>= 1) {
            c += __shfl_xor_sync(0xffffffffu, c, o);
            v += __shfl_xor_sync(0xffffffffu, v, o);
            r += __shfl_xor_sync(0xffffffffu, r, o);
        }
        if (lane == 0) { s_rl[wid] = c; s_rr[wid] = v; s_rn[wid] = r; }
        __syncthreads();
        if (i == 0) {
            float C = 0.0f, V = 0.0f, R = 0.0f;
            #pragma unroll
            for (int k = 0; k < 8; k++) { C += s_rl[k]; V += s_rr[k]; R += s_rn[k]; }
            out[0] = C / fmaxf(V, 1.0f) + R * (1.0f / (float)BB);
            g_done = 0;   // reset for next graph replay
        }
    }
}

extern "C" void kernel_launch(void* const* d_in, const int* in_sizes, int n_in,
                              void* d_out, int out_size)
{
    const float* pred   = (const float*)d_in[0];
    const float* target = (const float*)d_in[1];
    const void*  valid  = (const void*)d_in[2];
    float*       out    = (float*)d_out;

    fused_kernel<<<BB, NN>>>(pred, target, valid, out);
}

// round 4
// speedup vs baseline: 1.6615x; 1.0897x over previous
#include <cuda_runtime.h>

// RankCoxHazardLoss — B=512 rows, N=256 items.
// One CTA (512 threads) per row: thread (i,h) owns item i=tid&255 and the
// j-half h=tid>>8. Last CTA to finish reduces the per-row partials.

#define EPSF 1e-7f
static constexpr int BB  = 512;
static constexpr int NN  = 256;
static constexpr int TPB = 512;

__device__ float g_row_cox[BB];
__device__ float g_row_vb[BB];
__device__ float g_row_rank[BB];
__device__ unsigned int g_done = 0;

__global__ __launch_bounds__(TPB) void fused_kernel(
    const float* __restrict__ pred,
    const float* __restrict__ target,
    const void*  __restrict__ validp,
    float*       __restrict__ out)
{
    __shared__ float2 s_te[NN];     // (masked time, exp(pred))
    __shared__ float  s_r[NN];      // exp(-pred)
    __shared__ float4 s_dnr[TPB];   // per-(i,h) partial (den, np, rs, 0)
    __shared__ float  s_pd[TPB];    // per-(i,h) partial product
    __shared__ float  s_w0[16], s_w1[16], s_w2[16];
    __shared__ unsigned int s_islast;

    const int tid  = threadIdx.x;
    const int i    = tid & (NN - 1);
    const int h    = tid >> 8;          // j-half
    const int lane = tid & 31;
    const int wid  = tid >> 5;
    const int b    = blockIdx.x;
    const int idx  = b * NN + i;

    // ---- detect valid_mask dtype from first 512 words of the buffer ----
    const unsigned int w = ((const unsigned int*)validp)[tid];
    const int any_bf = __syncthreads_or((w == 0x3F803F80u) || (w == 0x00003F80u));
    const int any_f  = __syncthreads_or(w == 0x3F800000u);
    const int any_mb = __syncthreads_or((w & 0xFFFFFF00u) != 0u &&
                                        w != 0x3F800000u && w != 0x3F803F80u &&
                                        w != 0x00003F80u);
    bool v_i;
    if (any_bf)      v_i = ((const unsigned short*)validp)[idx] != 0;
    else if (any_f)  v_i = ((const float*)validp)[idx] != 0.0f;
    else if (any_mb) v_i = ((const unsigned char*)validp)[idx] != 0;
    else             v_i = ((const int*)validp)[idx] != 0;

    const float p_i  = pred[idx];
    const float t_i  = target[idx];
    const float tm_i = v_i ? t_i : -1.0f;

    // one MUFU per thread: h=0 does exp(p), h=1 does exp(-p)
    if (h == 0) s_te[i] = make_float2(tm_i, __expf(p_i));
    else        s_r[i]  = __expf(-p_i);

    // ---- block max masked time / valid count (h=0 contributes) ----
    float m  = (h == 0) ? tm_i : -1.0f;
    float vc = (h == 0 && v_i) ? 1.0f : 0.0f;
    #pragma unroll
    for (int o = 16; o; o >>= 1) {
        m  = fmaxf(m, __shfl_xor_sync(0xffffffffu, m, o));
        vc +=        __shfl_xor_sync(0xffffffffu, vc, o);
    }
    if (lane == 0) { s_w0[wid] = m; s_w1[wid] = vc; }
    __syncthreads();
    float bmax = s_w0[0], vcnt = s_w1[0];
    #pragma unroll
    for (int k = 1; k < 16; k++) { bmax = fmaxf(bmax, s_w0[k]); vcnt += s_w1[k]; }

    const float e_i = s_te[i].y;

    // ---- pass 1 over own j-half: den / np / rs (pure predicated ALU) ----
    // NOTE: uses t_i (not tm_i); results for invalid i are discarded below.
    const float4* te4 = (const float4*)s_te;
    const float4* r4  = (const float4*)s_r;
    float den0 = 0.0f, den1 = 0.0f, np0 = 0.0f, np1 = 0.0f, rs0 = 0.0f, rs1 = 0.0f;
    const int q0 = 32 * h;
    #pragma unroll 4
    for (int q = q0; q < q0 + 32; q++) {
        const float4 rr = r4[q];
        const float4 a  = te4[2 * q];
        const float4 c  = te4[2 * q + 1];
        { const bool k1 = a.x >= t_i; const bool tp = (a.x >= 0.0f) && !k1;
          if (k1) den0 += a.y; if (tp) np0 += 1.0f;
          if (tp && e_i > a.y) rs0 += rr.x; }
        { const bool k1 = a.z >= t_i; const bool tp = (a.z >= 0.0f) && !k1;
          if (k1) den1 += a.w; if (tp) np1 += 1.0f;
          if (tp && e_i > a.w) rs1 += rr.y; }
        { const bool k1 = c.x >= t_i; const bool tp = (c.x >= 0.0f) && !k1;
          if (k1) den0 += c.y; if (tp) np0 += 1.0f;
          if (tp && e_i > c.y) rs0 += rr.z; }
        { const bool k1 = c.z >= t_i; const bool tp = (c.z >= 0.0f) && !k1;
          if (k1) den1 += c.w; if (tp) np1 += 1.0f;
          if (tp && e_i > c.w) rs1 += rr.w; }
    }
    s_dnr[tid] = make_float4(den0 + den1, np0 + np1, rs0 + rs1, 0.0f);
    __syncthreads();

    const float4 PA = s_dnr[i];
    const float4 PB = s_dnr[i + NN];
    const float denT = PA.x + PB.x;
    const float npT  = PA.y + PB.y;
    const float rsT  = PA.z + PB.z;
    const float invden = 1.0f / denT;

    // ---- pass 2 over own j-half: product of surviving terms ----
    const float c1c = 1.0f + EPSF;
    const float c2c = 2.0f * EPSF;
    float pd0 = 1.0f, pd1 = 1.0f;
    const int k0 = 64 * h;
    #pragma unroll 8
    for (int k = k0; k < k0 + 64; k++) {
        const float4 a = te4[k];
        const float t0 = fmaxf(fmaf(-a.y, invden, c1c), c2c);
        const float t1 = fmaxf(fmaf(-a.w, invden, c1c), c2c);
        if (a.x >= t_i) pd0 *= t0;
        if (a.z >= t_i) pd1 *= t1;
    }
    s_pd[tid] = pd0 * pd1;
    __syncthreads();

    // ---- finalize per-i (h=0 only), then block reduce ----
    float loss = 0.0f, rankc = 0.0f, npq = 0.0f;
    if (h == 0) {
        const bool elim = (tm_i < bmax) && (tm_i > 0.0f) && v_i;
        if (elim) {
            const float prod = s_pd[i] * s_pd[i + NN];
            const float own  = fmaxf(fmaf(-e_i, invden, c1c), c2c); // j==i term
            loss = (__logf(denT) - p_i) - __logf(prod) + __logf(own);
        }
        if (v_i) { rankc = e_i * rsT; npq = npT; }
    }
    #pragma unroll
    for (int o = 16; o; o >>= 1) {
        loss  += __shfl_xor_sync(0xffffffffu, loss, o);
        rankc += __shfl_xor_sync(0xffffffffu, rankc, o);
        npq   += __shfl_xor_sync(0xffffffffu, npq, o);
    }
    if (lane == 0) { s_w0[wid] = loss; s_w1[wid] = rankc; s_w2[wid] = npq; }
    __syncthreads();
    if (tid == 0) {
        float tl = 0.0f, tr = 0.0f, tn = 0.0f;
        #pragma unroll
        for (int k = 0; k < 16; k++) { tl += s_w0[k]; tr += s_w1[k]; tn += s_w2[k]; }
        const float vb = (vcnt >= 2.0f) ? 1.0f : 0.0f;
        g_row_cox[b]  = vb * tl;
        g_row_vb[b]   = vb;
        g_row_rank[b] = tr / fmaxf(tn, 1.0f);
        __threadfence();
        const unsigned int t = atomicAdd(&g_done, 1u);
        s_islast = (t == (unsigned int)(BB - 1)) ? 1u : 0u;
    }
    __syncthreads();

    // ---- last block: final scalar reduction over the 512 rows ----
    if (s_islast) {
        float c = g_row_cox[tid];
        float v = g_row_vb[tid];
        float r = g_row_rank[tid];
        #pragma unroll
        for (int o = 16; o; o >>= 1) {
            c += __shfl_xor_sync(0xffffffffu, c, o);
            v += __shfl_xor_sync(0xffffffffu, v, o);
            r += __shfl_xor_sync(0xffffffffu, r, o);
        }
        if (lane == 0) { s_w0[wid] = c; s_w1[wid] = v; s_w2[wid] = r; }
        __syncthreads();
        if (tid == 0) {
            float C = 0.0f, V = 0.0f, R = 0.0f;
            #pragma unroll
            for (int k = 0; k < 16; k++) { C += s_w0[k]; V += s_w1[k]; R += s_w2[k]; }
            out[0] = C / fmaxf(V, 1.0f) + R * (1.0f / (float)BB);
            g_done = 0;   // reset for next graph replay
        }
    }
}

extern "C" void kernel_launch(void* const* d_in, const int* in_sizes, int n_in,
                              void* d_out, int out_size)
{
    const float* pred   = (const float*)d_in[0];
    const float* target = (const float*)d_in[1];
    const void*  valid  = (const void*)d_in[2];
    float*       out    = (float*)d_out;

    fused_kernel<<<BB, TPB>>>(pred, target, valid, out);
}

// round 5
// speedup vs baseline: 1.8462x; 1.1111x over previous
#include <cuda_runtime.h>

// RankCoxHazardLoss — B=512 rows, N=256. Sort-based restructure:
// each CTA (256 thr) ranks its row by masked time (unique u32 keys),
// scatters to sorted order, then: den = suffix-scan (O(N)),
// num_pairs = C(vcnt,2) closed form, pass2 product over suffix only,
// rank-violation sum over prefix only. Last CTA reduces to scalar.

#define EPSF 1e-7f
static constexpr int BB = 512;
static constexpr int NN = 256;

__device__ float g_row_cox[BB];
__device__ float g_row_vb[BB];
__device__ float g_row_rank[BB];
__device__ unsigned int g_done = 0;

__global__ __launch_bounds__(NN) void fused_kernel(
    const float* __restrict__ pred,
    const float* __restrict__ target,
    const void*  __restrict__ validp,
    float*       __restrict__ out)
{
    __shared__ unsigned int s_key[NN];
    __shared__ float s_e2[NN];   // exp(pred), sorted
    __shared__ float s_rz[NN];   // valid ? exp(-pred) : 0, sorted
    __shared__ float s_t2[NN];   // masked time, sorted
    __shared__ float s_p2[NN];   // pred, sorted
    __shared__ float s_w0[8], s_w1[8];
    __shared__ int   s_vc[8];
    __shared__ unsigned int s_islast;

    const int tid  = threadIdx.x;
    const int lane = tid & 31;
    const int wid  = tid >> 5;
    const int b    = blockIdx.x;
    const int idx  = b * NN + tid;

    // ---- valid_mask dtype detection (bit patterns of first 256 words) ----
    const unsigned int w = ((const unsigned int*)validp)[tid];
    const int any_bf = __syncthreads_or((w == 0x3F803F80u) || (w == 0x00003F80u));
    const int any_f  = __syncthreads_or(w == 0x3F800000u);
    const int any_mb = __syncthreads_or((w & 0xFFFFFF00u) != 0u &&
                                        w != 0x3F800000u && w != 0x3F803F80u &&
                                        w != 0x00003F80u);
    bool v_i;
    if (any_bf)      v_i = ((const unsigned short*)validp)[idx] != 0;
    else if (any_f)  v_i = ((const float*)validp)[idx] != 0.0f;
    else if (any_mb) v_i = ((const unsigned char*)validp)[idx] != 0;
    else             v_i = ((const int*)validp)[idx] != 0;

    const float p_i  = pred[idx];
    const float t_i  = target[idx];
    const float tm_i = v_i ? t_i : -1.0f;

    // ---- unique sortable key: ordered float bits, low 8 bits = index ----
    unsigned int u = __float_as_uint(tm_i);
    u ^= (unsigned int)((int)u >> 31) | 0x80000000u;
    const unsigned int key = (u & 0xFFFFFF00u) | (unsigned int)tid;
    s_key[tid] = key;

    // valid count via ballot
    const unsigned int bal = __ballot_sync(0xffffffffu, v_i);
    if (lane == 0) s_vc[wid] = __popc(bal);
    __syncthreads();
    int vcnt = 0;
    #pragma unroll
    for (int k = 0; k < 8; k++) vcnt += s_vc[k];
    const int ninv = NN - vcnt;

    // ---- rank = #{key_j < key_i} (keys strictly unique) ----
    const uint4* k4 = (const uint4*)s_key;
    int r0 = 0, r1 = 0;
    #pragma unroll 8
    for (int q = 0; q < NN / 4; q++) {
        const uint4 kk = k4[q];
        r0 += (kk.x < key); r1 += (kk.y < key);
        r0 += (kk.z < key); r1 += (kk.w < key);
    }
    const int rank = r0 + r1;

    // ---- scatter to sorted order ----
    const float e_i = __expf(p_i);
    s_e2[rank] = e_i;
    s_rz[rank] = v_i ? __expf(-p_i) : 0.0f;
    s_t2[rank] = tm_i;
    s_p2[rank] = p_i;
    __syncthreads();

    // thread tid now owns sorted slot k = tid
    const float E_k = s_e2[tid];
    const float T_k = s_t2[tid];
    const float P_k = s_p2[tid];
    const float bmax = s_t2[NN - 1];

    // ---- den_k = suffix sum of E over [k, 255] ----
    float sfx = E_k;
    #pragma unroll
    for (int o = 1; o < 32; o <<= 1) {
        const float t = __shfl_down_sync(0xffffffffu, sfx, o);
        if (lane + o < 32) sfx += t;
    }
    if (lane == 0) s_w0[wid] = sfx;   // warp total
    __syncthreads();
    float add = 0.0f;
    #pragma unroll
    for (int k2 = 7; k2 > 0; k2--) if (k2 > wid) add += s_w0[k2];
    const float den = sfx + add;
    const float invden = 1.0f / den;

    // ---- rank-violation sum over prefix [0, k): valid_j (rz=0 if not)
    //      and E_j < E_k  (== p_j < p_i) ----
    const float4* e4 = (const float4*)s_e2;
    const float4* z4 = (const float4*)s_rz;
    float rs = 0.0f;
    const int qhi = (wid + 1) * 8;         // warp-uniform bound: j < 32*wid+32
    #pragma unroll 4
    for (int q = 0; q < qhi; q++) {
        const float4 E = e4[q];
        const float4 Z = z4[q];
        const int j = q * 4;
        if (j + 0 < tid && E.x < E_k) rs += Z.x;
        if (j + 1 < tid && E.y < E_k) rs += Z.y;
        if (j + 2 < tid && E.z < E_k) rs += Z.z;
        if (j + 3 < tid && E.w < E_k) rs += Z.w;
    }

    // ---- pass 2: product of surviving terms over suffix [k, 255]
    //      (includes j==k; divided out below) ----
    const float c1c = 1.0f + EPSF;
    const float c2c = 2.0f * EPSF;
    float pd0 = 1.0f, pd1 = 1.0f;
    #pragma unroll 4
    for (int q = wid * 8; q < NN / 4; q++) {
        const float4 E = e4[q];
        const int j = q * 4;
        const float t0 = fmaxf(fmaf(-E.x, invden, c1c), c2c);
        const float t1 = fmaxf(fmaf(-E.y, invden, c1c), c2c);
        const float t2 = fmaxf(fmaf(-E.z, invden, c1c), c2c);
        const float t3 = fmaxf(fmaf(-E.w, invden, c1c), c2c);
        if (j + 0 >= tid) pd0 *= t0;
        if (j + 1 >= tid) pd1 *= t1;
        if (j + 2 >= tid) pd0 *= t2;
        if (j + 3 >= tid) pd1 *= t3;
    }

    // ---- finalize per sorted slot ----
    const bool valid_k = (tid >= ninv);
    const bool elim = valid_k && (T_k > 0.0f) && (T_k < bmax);
    float loss = 0.0f;
    if (elim) {
        const float own = fmaxf(fmaf(-E_k, invden, c1c), c2c);  // j==k term
        loss = (__logf(den) - P_k) - __logf(pd0 * pd1) + __logf(own);
    }
    float rankc = valid_k ? E_k * rs : 0.0f;

    // ---- block reduce (loss, rankc) ----
    #pragma unroll
    for (int o = 16; o; o >>= 1) {
        loss  += __shfl_xor_sync(0xffffffffu, loss, o);
        rankc += __shfl_xor_sync(0xffffffffu, rankc, o);
    }
    __syncthreads();                       // s_w0 reuse
    if (lane == 0) { s_w0[wid] = loss; s_w1[wid] = rankc; }
    __syncthreads();
    if (tid == 0) {
        float tl = 0.0f, tr = 0.0f;
        #pragma unroll
        for (int k = 0; k < 8; k++) { tl += s_w0[k]; tr += s_w1[k]; }
        const float fv = (float)vcnt;
        const float npairs = 0.5f * fv * (fv - 1.0f);   // C(vcnt,2), exact
        const float vb = (vcnt >= 2) ? 1.0f : 0.0f;
        g_row_cox[b]  = vb * tl;
        g_row_vb[b]   = vb;
        g_row_rank[b] = tr / fmaxf(npairs, 1.0f);
        __threadfence();
        const unsigned int t = atomicAdd(&g_done, 1u);
        s_islast = (t == (unsigned int)(BB - 1)) ? 1u : 0u;
    }
    __syncthreads();

    // ---- last block: final scalar reduction over 512 rows ----
    if (s_islast) {
        float c = g_row_cox[tid]  + g_row_cox[tid + NN];
        float v = g_row_vb[tid]   + g_row_vb[tid + NN];
        float r = g_row_rank[tid] + g_row_rank[tid + NN];
        #pragma unroll
        for (int o = 16; o; o >>= 1) {
            c += __shfl_xor_sync(0xffffffffu, c, o);
            v += __shfl_xor_sync(0xffffffffu, v, o);
            r += __shfl_xor_sync(0xffffffffu, r, o);
        }
        __syncthreads();
        if (lane == 0) { s_w0[wid] = c; s_w1[wid] = v; ((float*)s_vc)[wid] = r; }
        __syncthreads();
        if (tid == 0) {
            float C = 0.0f, V = 0.0f, R = 0.0f;
            #pragma unroll
            for (int k = 0; k < 8; k++) {
                C += s_w0[k]; V += s_w1[k]; R += ((float*)s_vc)[k];
            }
            out[0] = C / fmaxf(V, 1.0f) + R * (1.0f / (float)BB);
            g_done = 0;   // reset for next graph replay
        }
    }
}

extern "C" void kernel_launch(void* const* d_in, const int* in_sizes, int n_in,
                              void* d_out, int out_size)
{
    const float* pred   = (const float*)d_in[0];
    const float* target = (const float*)d_in[1];
    const void*  valid  = (const void*)d_in[2];
    float*       out    = (float*)d_out;

    fused_kernel<<<BB, NN>>>(pred, target, valid, out);
}